// round 1
// baseline (speedup 1.0000x reference)
#include <cuda_runtime.h>

#define NN 20000
#define NE 160000
#define HH 8
#define DKK 32
#define DD 256

// ---------------- scratch (static device arrays; no allocation) ----------------
__device__ float g_q[NN * DD];
__device__ float g_k[NN * DD];
__device__ float g_v[NN * DD];
__device__ float g_mk[NN * DD];
__device__ float g_val[3][NN * DD];
__device__ float g_cval[3][NN * DD];   // comb_pri pre-multiplied
__device__ float g_ea[3][NE * HH];     // exp(att)
__device__ float g_cea[3][NE * HH];    // exp(catt)
__device__ float g_sum[3][NN * HH];
__device__ float g_csum[3][NN * HH];

__device__ __forceinline__ void fma4(float4& a, float s, const float4 b) {
    a.x += s * b.x; a.y += s * b.y; a.z += s * b.z; a.w += s * b.w;
}

__device__ __forceinline__ void red_add_v4(float* p, float4 v) {
    asm volatile("red.global.add.v4.f32 [%0], {%1,%2,%3,%4};"
                 :: "l"(p), "f"(v.x), "f"(v.y), "f"(v.z), "f"(v.w) : "memory");
}

// ---------------- K0: zero output + softmax denominators ----------------
__global__ __launch_bounds__(256) void k_init(float* __restrict__ out) {
    int i = blockIdx.x * 256 + threadIdx.x;
    if (i < NN * DD) out[i] = 0.0f;
    if (i < 3 * NN * HH) {
        (&g_sum[0][0])[i]  = 0.0f;
        (&g_csum[0][0])[i] = 0.0f;
    }
}

// ---------------- K1a: q,k,v projections (tiled SGEMM) ----------------
// Block = 32 nodes. 256 threads = 8 warps; warp g owns nodes g*4..g*4+3,
// lane c owns cols {4c..4c+3} U {128+4c..128+4c+3}.
__global__ __launch_bounds__(256) void k_proj(
    const float* __restrict__ x,
    const float* __restrict__ Wq, const float* __restrict__ bq,
    const float* __restrict__ Wk, const float* __restrict__ bk,
    const float* __restrict__ Wv, const float* __restrict__ bv)
{
    __shared__ __align__(16) float xsT[256 * 36];  // [kk][node], stride 36 (16B-aligned rows)
    __shared__ __align__(16) float ws[8 * 256];    // 8 W rows staged

    const int tid   = threadIdx.x;
    const int node0 = blockIdx.x * 32;

    // xsT[kk][n] = x[(node0+n)*256 + kk]  (kk = tid, coalesced reads)
    #pragma unroll 4
    for (int n = 0; n < 32; n++)
        xsT[tid * 36 + n] = x[(size_t)(node0 + n) * 256 + tid];
    __syncthreads();

    const int g = tid >> 5;   // warp id -> node group
    const int c = tid & 31;   // lane -> column group

    const float* Wm[3] = {Wq, Wk, Wv};
    const float* Bm[3] = {bq, bk, bv};
    float*       Om[3] = {g_q, g_k, g_v};

    for (int m = 0; m < 3; m++) {
        float4 a0[4], a1[4];
        #pragma unroll
        for (int n = 0; n < 4; n++) { a0[n] = make_float4(0,0,0,0); a1[n] = make_float4(0,0,0,0); }
        const float* W = Wm[m];

        for (int kb = 0; kb < 32; kb++) {
            __syncthreads();
            #pragma unroll
            for (int i = 0; i < 8; i++)
                ws[i * 256 + tid] = W[(size_t)(kb * 8 + i) * 256 + tid];
            __syncthreads();
            #pragma unroll
            for (int r = 0; r < 8; r++) {
                float4 xv = *(const float4*)&xsT[(kb * 8 + r) * 36 + g * 4];
                float4 w0 = *(const float4*)&ws[r * 256 + c * 4];
                float4 w1 = *(const float4*)&ws[r * 256 + 128 + c * 4];
                fma4(a0[0], xv.x, w0); fma4(a1[0], xv.x, w1);
                fma4(a0[1], xv.y, w0); fma4(a1[1], xv.y, w1);
                fma4(a0[2], xv.z, w0); fma4(a1[2], xv.z, w1);
                fma4(a0[3], xv.w, w0); fma4(a1[3], xv.w, w1);
            }
        }

        float4 b0 = *(const float4*)(Bm[m] + c * 4);
        float4 b1 = *(const float4*)(Bm[m] + 128 + c * 4);
        float* O = Om[m];
        #pragma unroll
        for (int n = 0; n < 4; n++) {
            int node = node0 + g * 4 + n;
            float4 r0 = a0[n]; r0.x += b0.x; r0.y += b0.y; r0.z += b0.z; r0.w += b0.w;
            float4 r1 = a1[n]; r1.x += b1.x; r1.y += b1.y; r1.z += b1.z; r1.w += b1.w;
            *(float4*)&O[(size_t)node * 256 + c * 4]       = r0;
            *(float4*)&O[(size_t)node * 256 + 128 + c * 4] = r1;
        }
    }
}

// ---------------- K1b: per-head 32x32 transforms ----------------
// Grid (node_tiles, heads). Computes masked_k, val[e], cval[e]*comb_pri[e].
__global__ __launch_bounds__(256) void k_trans(
    const float* __restrict__ msg, const float* __restrict__ msg_cau,
    const float* __restrict__ cau_filter, const float* __restrict__ comb_pri,
    const float* __restrict__ time_emb, const int* __restrict__ cau_type)
{
    const int h     = blockIdx.y;
    const int node0 = blockIdx.x * 32;
    const int tid   = threadIdx.x;

    __shared__ __align__(16) float Fm[3][1024];
    __shared__ __align__(16) float Fc[3][1024];
    __shared__ __align__(16) float Ff[3][1024];
    __shared__ float kt[32 * 33];
    __shared__ float vt[32 * 33];
    __shared__ float te_s[32];
    __shared__ float cp_s[3 * 32];

    #pragma unroll
    for (int e = 0; e < 3; e++) {
        #pragma unroll
        for (int i = 0; i < 4; i++) {
            int idx = i * 256 + tid;
            Fm[e][idx] = msg[(size_t)(e * HH + h) * 1024 + idx];
            Fc[e][idx] = msg_cau[(size_t)(e * HH + h) * 1024 + idx];
            Ff[e][idx] = cau_filter[(size_t)(e * HH + h) * 1024 + idx];
        }
    }
    #pragma unroll
    for (int i = 0; i < 4; i++) {
        int lin = i * 256 + tid;
        int n = lin >> 5, d = lin & 31;
        kt[n * 33 + d] = g_k[(size_t)(node0 + n) * 256 + h * 32 + d];
        vt[n * 33 + d] = g_v[(size_t)(node0 + n) * 256 + h * 32 + d];
    }
    if (tid < 32) te_s[tid] = time_emb[h * 32 + tid];
    if (tid < 96) { int e = tid >> 5, f = tid & 31; cp_s[tid] = comb_pri[e * 256 + h * 32 + f]; }
    __syncthreads();

    const int n  = tid >> 3;
    const int fq = tid & 7;
    const int f0 = fq * 4;
    const int ct = cau_type[node0 + n];
    const float4* Ffp = (const float4*)Ff[ct];

    float4 mk = make_float4(0,0,0,0);
    float4 va[3], cv[3];
    #pragma unroll
    for (int e = 0; e < 3; e++) { va[e] = make_float4(0,0,0,0); cv[e] = make_float4(0,0,0,0); }

    #pragma unroll 8
    for (int d = 0; d < 32; d++) {
        float kv  = kt[n * 33 + d];
        float vv  = vt[n * 33 + d];
        float vtd = vv + te_s[d];
        float4 ff = Ffp[d * 8 + fq];
        fma4(mk, kv, ff);
        #pragma unroll
        for (int e = 0; e < 3; e++) {
            float4 fm = ((const float4*)Fm[e])[d * 8 + fq];
            fma4(va[e], vv, fm);
            float4 fc = ((const float4*)Fc[e])[d * 8 + fq];
            fma4(cv[e], vtd, fc);
        }
    }

    size_t o = (size_t)(node0 + n) * 256 + h * 32 + f0;
    *(float4*)&g_mk[o] = mk;
    #pragma unroll
    for (int e = 0; e < 3; e++) {
        *(float4*)&g_val[e][o] = va[e];
        float4 cp = *(const float4*)&cp_s[e * 32 + f0];
        cv[e].x *= cp.x; cv[e].y *= cp.y; cv[e].z *= cp.z; cv[e].w *= cp.w;
        *(float4*)&g_cval[e][o] = cv[e];
    }
}

// ---------------- K2: edge attention scores (softmax numerators + denominators) ----------------
// One warp per edge. lane = h*4 + j; lane covers 8 contiguous dims of head h.
// No segment-max pass: logits ~ N(0,1), exp() cannot overflow; softmax is shift-invariant.
__global__ __launch_bounds__(256) void k_att(
    const int* __restrict__ src, const int* __restrict__ dst,
    const float* __restrict__ pri, const float* __restrict__ pri_cau)
{
    int wid = blockIdx.x * 8 + (threadIdx.x >> 5);
    if (wid >= 3 * NE) return;
    int e = wid / NE;
    int i = wid - e * NE;
    int lane = threadIdx.x & 31;
    int h = lane >> 2, j = lane & 3;
    int s = src[e * NE + i], d = dst[e * NE + i];
    int off = h * 32 + j * 8;

    const float4* qp = (const float4*)(g_q  + (size_t)d * 256 + off);
    const float4* kp = (const float4*)(g_k  + (size_t)s * 256 + off);
    const float4* mp = (const float4*)(g_mk + (size_t)s * 256 + off);
    float4 q0 = qp[0], q1 = qp[1];
    float4 k0 = kp[0], k1 = kp[1];
    float4 m0 = mp[0], m1 = mp[1];

    float p  = q0.x*k0.x + q0.y*k0.y + q0.z*k0.z + q0.w*k0.w
             + q1.x*k1.x + q1.y*k1.y + q1.z*k1.z + q1.w*k1.w;
    float pc = q0.x*m0.x + q0.y*m0.y + q0.z*m0.z + q0.w*m0.w
             + q1.x*m1.x + q1.y*m1.y + q1.z*m1.z + q1.w*m1.w;
    p  += __shfl_xor_sync(0xffffffffu, p, 1);
    p  += __shfl_xor_sync(0xffffffffu, p, 2);
    pc += __shfl_xor_sync(0xffffffffu, pc, 1);
    pc += __shfl_xor_sync(0xffffffffu, pc, 2);

    const float inv = 0.17677669529663688f;  // 1/sqrt(32)
    float ea  = __expf(p  * pri[e * 8 + h]     * inv);
    float cea = __expf(pc * pri_cau[e * 8 + h] * inv);

    if (j == 0) {
        g_ea[e][i * 8 + h] = ea;
        atomicAdd(&g_sum[e][d * 8 + h], ea);
    } else if (j == 1) {
        g_cea[e][i * 8 + h] = cea;
        atomicAdd(&g_csum[e][d * 8 + h], cea);
    }
}

// ---------------- K4: weighted value scatter (vector reductions) ----------------
__global__ __launch_bounds__(256) void k_scatter(
    const int* __restrict__ src, const int* __restrict__ dst, float* __restrict__ out)
{
    int wid = blockIdx.x * 8 + (threadIdx.x >> 5);
    if (wid >= 3 * NE) return;
    int e = wid / NE;
    int i = wid - e * NE;
    int lane = threadIdx.x & 31;
    int h = lane >> 2, j = lane & 3;
    int s = src[e * NE + i], d = dst[e * NE + i];
    int off = h * 32 + j * 8;

    float wa = g_ea[e][i * 8 + h]  / g_sum[e][d * 8 + h]  * (1.0f / 3.0f);
    float wc = g_cea[e][i * 8 + h] / g_csum[e][d * 8 + h] * (1.0f / 3.0f);

    const float4* vp = (const float4*)(g_val[e]  + (size_t)s * 256 + off);
    const float4* cp = (const float4*)(g_cval[e] + (size_t)s * 256 + off);
    float4 v0 = vp[0], v1 = vp[1];
    float4 c0 = cp[0], c1 = cp[1];

    float4 r0 = make_float4(wa*v0.x + wc*c0.x, wa*v0.y + wc*c0.y,
                            wa*v0.z + wc*c0.z, wa*v0.w + wc*c0.w);
    float4 r1 = make_float4(wa*v1.x + wc*c1.x, wa*v1.y + wc*c1.y,
                            wa*v1.z + wc*c1.z, wa*v1.w + wc*c1.w);

    float* po = out + (size_t)d * 256 + off;
    red_add_v4(po, r0);
    red_add_v4(po + 4, r1);
}

// ---------------- K5: relu ----------------
__global__ __launch_bounds__(256) void k_relu(float* __restrict__ out) {
    int i = blockIdx.x * 256 + threadIdx.x;
    if (i < NN * DD) {
        float v = out[i];
        out[i] = v > 0.0f ? v : 0.0f;
    }
}

extern "C" void kernel_launch(void* const* d_in, const int* in_sizes, int n_in,
                              void* d_out, int out_size)
{
    const float* x    = (const float*)d_in[0];
    const float* Wk_  = (const float*)d_in[1];
    const float* bk_  = (const float*)d_in[2];
    const float* Wq_  = (const float*)d_in[3];
    const float* bq_  = (const float*)d_in[4];
    const float* Wv_  = (const float*)d_in[5];
    const float* bv_  = (const float*)d_in[6];
    const float* pri  = (const float*)d_in[7];
    const float* msg  = (const float*)d_in[8];
    const float* pric = (const float*)d_in[9];
    const float* msgc = (const float*)d_in[10];
    const float* cpri = (const float*)d_in[11];
    const float* cauf = (const float*)d_in[12];
    const float* temb = (const float*)d_in[13];
    const int*   ctyp = (const int*)d_in[14];
    const int*   src  = (const int*)d_in[15];
    const int*   dst  = (const int*)d_in[16];
    float* out = (float*)d_out;

    k_init<<<(NN * DD) / 256, 256>>>(out);
    k_proj<<<NN / 32, 256>>>(x, Wq_, bq_, Wk_, bk_, Wv_, bv_);
    k_trans<<<dim3(NN / 32, HH), 256>>>(msg, msgc, cauf, cpri, temb, ctyp);
    k_att<<<(3 * NE) / 8, 256>>>(src, dst, pri, pric);
    k_scatter<<<(3 * NE) / 8, 256>>>(src, dst, out);
    k_relu<<<(NN * DD) / 256, 256>>>(out);
}